// round 16
// baseline (speedup 1.0000x reference)
#include <cuda_runtime.h>
#include <cuda_bf16.h>
#include <cuda_fp16.h>
#include <cstdint>
#include <math.h>

// ---------------------------------------------------------------------------
// Problem constants
// ---------------------------------------------------------------------------
constexpr int Bb = 2;
constexpr int Ss = 2048;
constexpr int Dd = 1024;
constexpr int Hh = 16;
constexpr int DK = 64;
constexpr int Mrows = Bb * Ss;           // 4096
constexpr float CEXP = 0.18033688f;      // (1/sqrt(64)) * log2(e)

// ---------------------------------------------------------------------------
// Scratch (device globals)
// ---------------------------------------------------------------------------
__device__ __half g_qkvf[3][(size_t)Mrows * Dd];
__device__ __half g_wf[4][(size_t)Dd * Dd];
__device__ __half g_ohf[(size_t)Mrows * Dd];
__device__ __half g_olf[(size_t)Mrows * Dd];
__device__ __half g_QKV[3][(size_t)32 * Ss * DK];   // Q pre-scaled by CEXP

// ---------------------------------------------------------------------------
// mma.sync / ldmatrix / cp.async helpers
// ---------------------------------------------------------------------------
__device__ __forceinline__ uint32_t smem_u32(const void* p) {
    uint32_t a;
    asm("{ .reg .u64 t; cvta.to.shared.u64 t, %1; cvt.u32.u64 %0, t; }"
        : "=r"(a) : "l"(p));
    return a;
}
__device__ __forceinline__ void ldm_x4(uint32_t* r, uint32_t addr) {
    asm volatile("ldmatrix.sync.aligned.m8n8.x4.shared.b16 {%0,%1,%2,%3}, [%4];"
                 : "=r"(r[0]), "=r"(r[1]), "=r"(r[2]), "=r"(r[3]) : "r"(addr));
}
__device__ __forceinline__ void ldm_x4_t(uint32_t* r, uint32_t addr) {
    asm volatile("ldmatrix.sync.aligned.m8n8.x4.trans.shared.b16 {%0,%1,%2,%3}, [%4];"
                 : "=r"(r[0]), "=r"(r[1]), "=r"(r[2]), "=r"(r[3]) : "r"(addr));
}
__device__ __forceinline__ void mma16816h(float* c, const uint32_t* a,
                                          uint32_t b0, uint32_t b1) {
    asm volatile(
        "mma.sync.aligned.m16n8k16.row.col.f32.f16.f16.f32 "
        "{%0,%1,%2,%3}, {%4,%5,%6,%7}, {%8,%9}, {%0,%1,%2,%3};"
        : "+f"(c[0]), "+f"(c[1]), "+f"(c[2]), "+f"(c[3])
        : "r"(a[0]), "r"(a[1]), "r"(a[2]), "r"(a[3]), "r"(b0), "r"(b1));
}
__device__ __forceinline__ void cp16(uint32_t dst, const void* src) {
    asm volatile("cp.async.cg.shared.global [%0], [%1], 16;"
                 :: "r"(dst), "l"(src) : "memory");
}
__device__ __forceinline__ void cp_commit() {
    asm volatile("cp.async.commit_group;" ::: "memory");
}
template <int N>
__device__ __forceinline__ void cp_wait() {
    asm volatile("cp.async.wait_group %0;" :: "n"(N) : "memory");
}
template <int ROWB>
__device__ __forceinline__ uint32_t fragA(uint32_t base, int row0, int kb0, int lane) {
    int r = row0 + ((lane >> 3) & 1) * 8 + (lane & 7);
    int kb = kb0 + (lane >> 4) * 16;
    return base + r * ROWB + kb;
}
template <int ROWB>
__device__ __forceinline__ uint32_t fragT(uint32_t base, int k0, int nb0, int lane) {
    int r = k0 + ((lane >> 4) & 1) * 8 + (lane & 7);
    int cb = nb0 + ((lane >> 3) & 1) * 16;
    return base + r * ROWB + cb;
}
__device__ __forceinline__ uint32_t packh2(float lo, float hi) {
    uint32_t r;
    asm("cvt.rn.f16x2.f32 %0, %1, %2;" : "=r"(r) : "f"(hi), "f"(lo));
    return r;
}
__device__ __forceinline__ uint32_t ex2h2(uint32_t x) {
    uint32_t r;
    asm("ex2.approx.f16x2 %0, %1;" : "=r"(r) : "r"(x));
    return r;
}

// ---------------------------------------------------------------------------
// Converts
// ---------------------------------------------------------------------------
__global__ __launch_bounds__(256)
void cvt_f16_3(const float* __restrict__ q, const float* __restrict__ k,
               const float* __restrict__ v) {
    const float* srcs[3] = {q, k, v};
    const float* x = srcs[blockIdx.z];
    __half* o = g_qkvf[blockIdx.z];
    int i = (blockIdx.x * 256 + threadIdx.x) * 4;
    float4 val = *(const float4*)(x + i);
    uint2 r;
    r.x = packh2(val.x, val.y);
    r.y = packh2(val.z, val.w);
    *(uint2*)(o + i) = r;
}

__global__ __launch_bounds__(256)
void cvt_f16T_4(const float* __restrict__ Wq, const float* __restrict__ Wk,
                const float* __restrict__ Wv, const float* __restrict__ Wo) {
    const float* srcs[4] = {Wq, Wk, Wv, Wo};
    const float* W = srcs[blockIdx.z];
    __half* oT = g_wf[blockIdx.z];
    __shared__ float t[32][33];
    int tx = threadIdx.x, ty = threadIdx.y;
    int n0 = blockIdx.x * 32, k0 = blockIdx.y * 32;
#pragma unroll
    for (int r = 0; r < 4; r++)
        t[ty + r * 8][tx] = W[(size_t)(k0 + ty + r * 8) * Dd + n0 + tx];
    __syncthreads();
#pragma unroll
    for (int r = 0; r < 4; r++) {
        int n = n0 + ty + r * 8;
        oT[(size_t)n * Dd + k0 + tx] = __float2half_rn(t[tx][ty + r * 8]);
    }
}

// ---------------------------------------------------------------------------
// Shared tile constants
// ---------------------------------------------------------------------------
constexpr int ROW64 = 144;
constexpr int ARR64 = 128 * ROW64;         // 18432

// ---------------------------------------------------------------------------
// Merged fp16 QKV projection GEMM, k-chunk 64, occ 2 (unchanged from R15)
// ---------------------------------------------------------------------------
constexpr int F16_BUF_B = 2 * ARR64;
constexpr int F16_SMEM = 2 * F16_BUF_B;    // 73728

__global__ __launch_bounds__(256, 2)
void gemm_f16_qkv() {
    extern __shared__ char smem[];
    const uint32_t sbase = smem_u32(smem);
    const int tid = threadIdx.x;
    const int lane = tid & 31;
    const int wid = tid >> 5;
    const int wm = wid >> 2;
    const int wn = wid & 3;
    const int bm = blockIdx.y * 128;
    const int bn = blockIdx.x * 128;
    const int z = blockIdx.z;

    const __half* A = g_qkvf[z];
    const __half* B = g_wf[z];
    __half* Chf = g_QKV[z];
    const float escale = (z == 0) ? CEXP : 1.0f;

    auto load_chunk = [&](int c, int b) {
        const int k0 = c * 64;
        const uint32_t dst0 = sbase + b * F16_BUF_B;
        const int row = tid >> 1;
        const __half* srcs[2] = {A + (size_t)(bm + row) * Dd + k0,
                                 B + (size_t)(bn + row) * Dd + k0};
#pragma unroll
        for (int a2 = 0; a2 < 2; a2++) {
#pragma unroll
            for (int j = 0; j < 4; j++) {
                int cch = (tid & 1) * 4 + j;
                cp16(dst0 + a2 * ARR64 + row * ROW64 + cch * 16,
                     srcs[a2] + cch * 8);
            }
        }
        cp_commit();
    };

    float acc[4][4][4];
#pragma unroll
    for (int i = 0; i < 4; i++)
#pragma unroll
        for (int j = 0; j < 4; j++)
#pragma unroll
            for (int r = 0; r < 4; r++) acc[i][j][r] = 0.0f;

    auto compute = [&](int b) {
        const uint32_t base = sbase + b * F16_BUF_B;
        const uint32_t aB = base;
        const uint32_t bB = base + ARR64;
#pragma unroll
        for (int s = 0; s < 4; s++) {
            const int kb = s * 32;
            uint32_t af[4][4];
#pragma unroll
            for (int i = 0; i < 4; i++)
                ldm_x4(af[i], fragA<ROW64>(aB, wm * 64 + i * 16, kb, lane));
#pragma unroll
            for (int nb = 0; nb < 2; nb++) {
                uint32_t bf[4];
                ldm_x4(bf, fragA<ROW64>(bB, wn * 32 + nb * 16, kb, lane));
#pragma unroll
                for (int i = 0; i < 4; i++) {
                    mma16816h(acc[i][nb * 2 + 0], af[i], bf[0], bf[2]);
                    mma16816h(acc[i][nb * 2 + 1], af[i], bf[1], bf[3]);
                }
            }
        }
    };

    constexpr int NCHUNK = Dd / 64;
    load_chunk(0, 0);
    for (int c = 0; c < NCHUNK; c++) {
        if (c + 1 < NCHUNK) {
            load_chunk(c + 1, (c + 1) & 1);
            cp_wait<1>();
        } else {
            cp_wait<0>();
        }
        __syncthreads();
        compute(c & 1);
        __syncthreads();
    }

    const int g = lane >> 2;
    const int tg = lane & 3;
#pragma unroll
    for (int i = 0; i < 4; i++) {
        int r0 = bm + wm * 64 + i * 16 + g;
#pragma unroll
        for (int j = 0; j < 4; j++) {
            int col = bn + wn * 32 + j * 8 + tg * 2;
            int h = col >> 6, dk = col & 63;
#pragma unroll
            for (int half = 0; half < 2; half++) {
                int r = r0 + half * 8;
                int b_ = r >> 11, s = r & 2047;
                size_t addr = (((size_t)(b_ * Hh + h)) * Ss + s) * DK + dk;
                *(uint32_t*)(Chf + addr) =
                    packh2(acc[i][j][half * 2] * escale,
                           acc[i][j][half * 2 + 1] * escale);
            }
        }
    }
}

// ---------------------------------------------------------------------------
// Wo GEMM: fp16-split 2-product, k-chunk 64, NOW occupancy 2.
// ---------------------------------------------------------------------------
constexpr int WO_BUF_B = 3 * ARR64;                // 55296
constexpr int WO_SMEM = 2 * WO_BUF_B;              // 110592 (x2 CTAs = 216 KB)

__global__ __launch_bounds__(256, 2)
void gemm_wo(const __half* __restrict__ Ahi, const __half* __restrict__ Alo,
             const __half* __restrict__ B, float* __restrict__ C) {
    extern __shared__ char smem[];
    const uint32_t sbase = smem_u32(smem);
    const int tid = threadIdx.x;
    const int lane = tid & 31;
    const int wid = tid >> 5;
    const int wm = wid >> 2;
    const int wn = wid & 3;
    const int bm = blockIdx.y * 128;
    const int bn = blockIdx.x * 128;

    auto load_chunk = [&](int c, int b) {
        const int k0 = c * 64;
        const uint32_t dst0 = sbase + b * WO_BUF_B;
        const int row = tid >> 1;
        const __half* srcs[3] = {Ahi + (size_t)(bm + row) * Dd + k0,
                                 Alo + (size_t)(bm + row) * Dd + k0,
                                 B + (size_t)(bn + row) * Dd + k0};
#pragma unroll
        for (int a3 = 0; a3 < 3; a3++) {
#pragma unroll
            for (int j = 0; j < 4; j++) {
                int cch = (tid & 1) * 4 + j;
                cp16(dst0 + a3 * ARR64 + row * ROW64 + cch * 16,
                     srcs[a3] + cch * 8);
            }
        }
        cp_commit();
    };

    float acc[4][4][4];
#pragma unroll
    for (int i = 0; i < 4; i++)
#pragma unroll
        for (int j = 0; j < 4; j++)
#pragma unroll
            for (int r = 0; r < 4; r++) acc[i][j][r] = 0.0f;

    auto compute = [&](int b) {
        const uint32_t base = sbase + b * WO_BUF_B;
        const uint32_t aHiB = base;
        const uint32_t aLoB = base + ARR64;
        const uint32_t bB = base + 2 * ARR64;
#pragma unroll
        for (int s = 0; s < 4; s++) {
            const int kb = s * 32;
            uint32_t ahi[4][4], alo[4][4];
#pragma unroll
            for (int i = 0; i < 4; i++) {
                ldm_x4(ahi[i], fragA<ROW64>(aHiB, wm * 64 + i * 16, kb, lane));
                ldm_x4(alo[i], fragA<ROW64>(aLoB, wm * 64 + i * 16, kb, lane));
            }
#pragma unroll
            for (int nb = 0; nb < 2; nb++) {
                uint32_t bf[4];
                ldm_x4(bf, fragA<ROW64>(bB, wn * 32 + nb * 16, kb, lane));
#pragma unroll
                for (int i = 0; i < 4; i++) {
                    mma16816h(acc[i][nb * 2 + 0], ahi[i], bf[0], bf[2]);
                    mma16816h(acc[i][nb * 2 + 1], ahi[i], bf[1], bf[3]);
                    mma16816h(acc[i][nb * 2 + 0], alo[i], bf[0], bf[2]);
                    mma16816h(acc[i][nb * 2 + 1], alo[i], bf[1], bf[3]);
                }
            }
        }
    };

    constexpr int NCHUNK = Dd / 64;
    load_chunk(0, 0);
    for (int c = 0; c < NCHUNK; c++) {
        if (c + 1 < NCHUNK) {
            load_chunk(c + 1, (c + 1) & 1);
            cp_wait<1>();
        } else {
            cp_wait<0>();
        }
        __syncthreads();
        compute(c & 1);
        __syncthreads();
    }

    const int g = lane >> 2;
    const int tg = lane & 3;
#pragma unroll
    for (int i = 0; i < 4; i++) {
        int r0 = bm + wm * 64 + i * 16 + g;
#pragma unroll
        for (int j = 0; j < 4; j++) {
            int col = bn + wn * 32 + j * 8 + tg * 2;
            *(float2*)(C + (size_t)r0 * Dd + col) =
                make_float2(acc[i][j][0], acc[i][j][1]);
            *(float2*)(C + (size_t)(r0 + 8) * Dd + col) =
                make_float2(acc[i][j][2], acc[i][j][3]);
        }
    }
}

// ---------------------------------------------------------------------------
// Tensor-core flash attention, 3-STAGE cp.async pipeline, occ 2.
// Fixed-shift softmax (Q pre-scaled), QK/PV 1-product, L via ones-column.
// ---------------------------------------------------------------------------
constexpr int AROW = 144;
constexpr int VROW = 176;
constexpr int Q_TILE_B = 128 * AROW;             // 18432
constexpr int K_TILE_B = 64 * AROW;              // 9216
constexpr int V_TILE_B = 64 * VROW;              // 11264
constexpr int ATT_BUF_B = K_TILE_B + V_TILE_B;   // 20480
constexpr int NSTAGE = 3;
constexpr int ATT_SMEM = Q_TILE_B + NSTAGE * ATT_BUF_B;  // 79872
constexpr uint32_t ONES2 = 0x3C003C00u;

__global__ __launch_bounds__(256, 2)
void attn_mma() {
    extern __shared__ char smem[];
    const uint32_t sb = smem_u32(smem);
    const int tid = threadIdx.x;
    const int lane = tid & 31;
    const int w = tid >> 5;
    const int bh = blockIdx.y;
    const int qt = blockIdx.x;
    const int b = bh >> 4, h = bh & 15;

    const __half* Qg = g_QKV[0] + (size_t)bh * Ss * DK + qt * 128 * DK;
    const __half* Kg = g_QKV[1] + (size_t)bh * Ss * DK;
    const __half* Vg = g_QKV[2] + (size_t)bh * Ss * DK;

    const uint32_t sQ = sb;

    auto load_kv = [&](int kt, int buf) {
        const uint32_t base = sb + Q_TILE_B + buf * ATT_BUF_B;
        {
            const char* src = (const char*)Kg + (size_t)kt * 64 * DK * 2;
#pragma unroll
            for (int p = 0; p < 2; p++) {
                int idx = tid + p * 256;
                int r = idx >> 3, c = idx & 7;
                cp16(base + r * AROW + c * 16, src + (r * DK + c * 8) * 2);
            }
        }
        {
            const char* src = (const char*)Vg + (size_t)kt * 64 * DK * 2;
#pragma unroll
            for (int p = 0; p < 2; p++) {
                int idx = tid + p * 256;
                int r = idx >> 3, c = idx & 7;
                cp16(base + K_TILE_B + r * VROW + c * 16,
                     src + (r * DK + c * 8) * 2);
            }
        }
        cp_commit();
    };

    // Q tile + ones columns (all 3 stages)
#pragma unroll
    for (int p = 0; p < 4; p++) {
        int idx = tid + p * 256;
        int r = idx >> 3, c = idx & 7;
        cp16(sQ + r * AROW + c * 16, Qg + r * DK + c * 8);
    }
    if (tid < 192) {
        int r = tid & 63, buf = tid >> 6;   // 3 stages x 64 rows
        uint32_t addr = sb + Q_TILE_B + buf * ATT_BUF_B + K_TILE_B + r * VROW + 128;
        asm volatile("st.shared.v4.b32 [%0], {%1, %1, %1, %1};"
                     :: "r"(addr), "r"(ONES2) : "memory");
    }
    load_kv(0, 0);
    load_kv(1, 1);
    cp_wait<1>();        // stage 0 (and Q, issued before it) complete
    __syncthreads();

    uint32_t qf[4][4];
#pragma unroll
    for (int s = 0; s < 4; s++)
        ldm_x4(qf[s], fragA<AROW>(sQ, w * 16, s * 32, lane));

    float Oacc[8][4];
    float Lacc[4];
#pragma unroll
    for (int j = 0; j < 8; j++)
#pragma unroll
        for (int r = 0; r < 4; r++) Oacc[j][r] = 0.0f;
#pragma unroll
    for (int r = 0; r < 4; r++) Lacc[r] = 0.0f;

    constexpr int NT = Ss / 64;   // 32
    for (int kt = 0; kt < NT; kt++) {
        // prefetch kt+2 into stage (kt+2)%3 (buffer last used by tile kt-1,
        // whose compute finished before the trailing barrier of iter kt-1)
        if (kt + 2 < NT) {
            load_kv(kt + 2, (kt + 2) % NSTAGE);
            cp_wait<2>();             // tile kt complete (kt+1, kt+2 pending)
        } else if (kt + 1 < NT) {
            cp_wait<1>();
        } else {
            cp_wait<0>();
        }
        __syncthreads();

        const uint32_t base = sb + Q_TILE_B + (kt % NSTAGE) * ATT_BUF_B;
        const uint32_t kT = base, vT = base + K_TILE_B;

        float sfr[8][4];
#pragma unroll
        for (int j = 0; j < 8; j++)
#pragma unroll
            for (int r = 0; r < 4; r++) sfr[j][r] = 0.0f;

#pragma unroll
        for (int s = 0; s < 4; s++) {
            const int kb = s * 32;
#pragma unroll
            for (int nb = 0; nb < 4; nb++) {
                uint32_t k4[4];
                ldm_x4(k4, fragA<AROW>(kT, nb * 16, kb, lane));
                mma16816h(sfr[nb * 2 + 0], qf[s], k4[0], k4[2]);
                mma16816h(sfr[nb * 2 + 1], qf[s], k4[1], k4[3]);
            }
        }

        uint32_t p2[8][2];
#pragma unroll
        for (int j = 0; j < 8; j++) {
            uint32_t t0 = packh2(sfr[j][0], sfr[j][1]);
            uint32_t t1 = packh2(sfr[j][2], sfr[j][3]);
            p2[j][0] = ex2h2(t0);
            p2[j][1] = ex2h2(t1);
        }

#pragma unroll
        for (int st = 0; st < 4; st++) {
            uint32_t pa[4] = {p2[2 * st][0], p2[2 * st][1],
                              p2[2 * st + 1][0], p2[2 * st + 1][1]};
#pragma unroll
            for (int nb = 0; nb < 4; nb++) {
                uint32_t v4[4];
                ldm_x4_t(v4, fragT<VROW>(vT, st * 16, nb * 32, lane));
                mma16816h(Oacc[nb * 2 + 0], pa, v4[0], v4[2]);
                mma16816h(Oacc[nb * 2 + 1], pa, v4[1], v4[3]);
            }
            mma16816h(Lacc, pa, ONES2, ONES2);
        }
        __syncthreads();
    }

    // ---- epilogue: normalize, split to fp16 hi/lo, write [B,S,D]
    const float inv0 = 1.0f / Lacc[0];
    const float inv1 = 1.0f / Lacc[2];
    const int g = lane >> 2;
    const int t = lane & 3;
    const int row0 = qt * 128 + w * 16 + g;
    const size_t gbase0 = ((size_t)b * Ss + row0) * Dd + h * 64;
    const size_t gbase1 = gbase0 + 8 * Dd;
#pragma unroll
    for (int j = 0; j < 8; j++) {
        int col = j * 8 + t * 2;
        float o00 = Oacc[j][0] * inv0, o01 = Oacc[j][1] * inv0;
        float o10 = Oacc[j][2] * inv1, o11 = Oacc[j][3] * inv1;
        __half h00 = __float2half_rn(o00), h01 = __float2half_rn(o01);
        __half h10 = __float2half_rn(o10), h11 = __float2half_rn(o11);
        *(uint32_t*)(g_ohf + gbase0 + col) =
            packh2(__half2float(h00), __half2float(h01));
        *(uint32_t*)(g_olf + gbase0 + col) =
            packh2(o00 - __half2float(h00), o01 - __half2float(h01));
        *(uint32_t*)(g_ohf + gbase1 + col) =
            packh2(__half2float(h10), __half2float(h11));
        *(uint32_t*)(g_olf + gbase1 + col) =
            packh2(o10 - __half2float(h10), o11 - __half2float(h11));
    }
}

// ---------------------------------------------------------------------------
// Launch
// ---------------------------------------------------------------------------
extern "C" void kernel_launch(void* const* d_in, const int* in_sizes, int n_in,
                              void* d_out, int out_size) {
    const float* q  = (const float*)d_in[0];
    const float* k  = (const float*)d_in[1];
    const float* v  = (const float*)d_in[2];
    const float* Wq = (const float*)d_in[3];
    const float* Wk = (const float*)d_in[4];
    const float* Wv = (const float*)d_in[5];
    const float* Wo = (const float*)d_in[6];
    float* out = (float*)d_out;

    __half *ohf, *olf, *wf;
    cudaGetSymbolAddress((void**)&ohf, g_ohf);
    cudaGetSymbolAddress((void**)&olf, g_olf);
    cudaGetSymbolAddress((void**)&wf, g_wf);
    const size_t WSTRIDE = (size_t)Dd * Dd;

    cudaFuncSetAttribute(attn_mma,
                         cudaFuncAttributeMaxDynamicSharedMemorySize, ATT_SMEM);
    cudaFuncSetAttribute(gemm_f16_qkv,
                         cudaFuncAttributeMaxDynamicSharedMemorySize, F16_SMEM);
    cudaFuncSetAttribute(gemm_wo,
                         cudaFuncAttributeMaxDynamicSharedMemorySize, WO_SMEM);

    const int cvt_blocks = Mrows * Dd / (256 * 4);
    cvt_f16_3<<<dim3(cvt_blocks, 1, 3), 256>>>(q, k, v);

    dim3 tB(32, 8), tG4(Dd / 32, Dd / 32, 4);
    cvt_f16T_4<<<tG4, tB>>>(Wq, Wk, Wv, Wo);

    gemm_f16_qkv<<<dim3(Dd / 128, Mrows / 128, 3), 256, F16_SMEM>>>();

    attn_mma<<<dim3(Ss / 128, Bb * Hh), 256, ATT_SMEM>>>();

    gemm_wo<<<dim3(Dd / 128, Mrows / 128), 256, WO_SMEM>>>(
        ohf, olf, wf + 3 * WSTRIDE, out);
}

// round 17
// speedup vs baseline: 1.0463x; 1.0463x over previous
#include <cuda_runtime.h>
#include <cuda_bf16.h>
#include <cuda_fp16.h>
#include <cstdint>
#include <math.h>

// ---------------------------------------------------------------------------
// Problem constants
// ---------------------------------------------------------------------------
constexpr int Bb = 2;
constexpr int Ss = 2048;
constexpr int Dd = 1024;
constexpr int Hh = 16;
constexpr int DK = 64;
constexpr int Mrows = Bb * Ss;           // 4096
constexpr float CEXP = 0.18033688f;      // (1/sqrt(64)) * log2(e)

// ---------------------------------------------------------------------------
// Scratch (device globals)
// ---------------------------------------------------------------------------
__device__ __half g_qkvf[3][(size_t)Mrows * Dd];
__device__ __half g_wf[4][(size_t)Dd * Dd];
__device__ __half g_ohf[(size_t)Mrows * Dd];
__device__ __half g_olf[(size_t)Mrows * Dd];
__device__ __half g_QKV[3][(size_t)32 * Ss * DK];   // Q pre-scaled by CEXP

// ---------------------------------------------------------------------------
// mma.sync / ldmatrix / cp.async helpers
// ---------------------------------------------------------------------------
__device__ __forceinline__ uint32_t smem_u32(const void* p) {
    uint32_t a;
    asm("{ .reg .u64 t; cvta.to.shared.u64 t, %1; cvt.u32.u64 %0, t; }"
        : "=r"(a) : "l"(p));
    return a;
}
__device__ __forceinline__ void ldm_x4(uint32_t* r, uint32_t addr) {
    asm volatile("ldmatrix.sync.aligned.m8n8.x4.shared.b16 {%0,%1,%2,%3}, [%4];"
                 : "=r"(r[0]), "=r"(r[1]), "=r"(r[2]), "=r"(r[3]) : "r"(addr));
}
__device__ __forceinline__ void ldm_x4_t(uint32_t* r, uint32_t addr) {
    asm volatile("ldmatrix.sync.aligned.m8n8.x4.trans.shared.b16 {%0,%1,%2,%3}, [%4];"
                 : "=r"(r[0]), "=r"(r[1]), "=r"(r[2]), "=r"(r[3]) : "r"(addr));
}
__device__ __forceinline__ void mma16816h(float* c, const uint32_t* a,
                                          uint32_t b0, uint32_t b1) {
    asm volatile(
        "mma.sync.aligned.m16n8k16.row.col.f32.f16.f16.f32 "
        "{%0,%1,%2,%3}, {%4,%5,%6,%7}, {%8,%9}, {%0,%1,%2,%3};"
        : "+f"(c[0]), "+f"(c[1]), "+f"(c[2]), "+f"(c[3])
        : "r"(a[0]), "r"(a[1]), "r"(a[2]), "r"(a[3]), "r"(b0), "r"(b1));
}
__device__ __forceinline__ void cp16(uint32_t dst, const void* src) {
    asm volatile("cp.async.cg.shared.global [%0], [%1], 16;"
                 :: "r"(dst), "l"(src) : "memory");
}
__device__ __forceinline__ void cp_commit() {
    asm volatile("cp.async.commit_group;" ::: "memory");
}
template <int N>
__device__ __forceinline__ void cp_wait() {
    asm volatile("cp.async.wait_group %0;" :: "n"(N) : "memory");
}
template <int ROWB>
__device__ __forceinline__ uint32_t fragA(uint32_t base, int row0, int kb0, int lane) {
    int r = row0 + ((lane >> 3) & 1) * 8 + (lane & 7);
    int kb = kb0 + (lane >> 4) * 16;
    return base + r * ROWB + kb;
}
template <int ROWB>
__device__ __forceinline__ uint32_t fragT(uint32_t base, int k0, int nb0, int lane) {
    int r = k0 + ((lane >> 4) & 1) * 8 + (lane & 7);
    int cb = nb0 + ((lane >> 3) & 1) * 16;
    return base + r * ROWB + cb;
}
__device__ __forceinline__ uint32_t packh2(float lo, float hi) {
    uint32_t r;
    asm("cvt.rn.f16x2.f32 %0, %1, %2;" : "=r"(r) : "f"(hi), "f"(lo));
    return r;
}
__device__ __forceinline__ uint32_t ex2h2(uint32_t x) {
    uint32_t r;
    asm("ex2.approx.f16x2 %0, %1;" : "=r"(r) : "r"(x));
    return r;
}

// ---------------------------------------------------------------------------
// Converts
// ---------------------------------------------------------------------------
__global__ __launch_bounds__(256)
void cvt_f16_3(const float* __restrict__ q, const float* __restrict__ k,
               const float* __restrict__ v) {
    const float* srcs[3] = {q, k, v};
    const float* x = srcs[blockIdx.z];
    __half* o = g_qkvf[blockIdx.z];
    int i = (blockIdx.x * 256 + threadIdx.x) * 4;
    float4 val = *(const float4*)(x + i);
    uint2 r;
    r.x = packh2(val.x, val.y);
    r.y = packh2(val.z, val.w);
    *(uint2*)(o + i) = r;
}

__global__ __launch_bounds__(256)
void cvt_f16T_4(const float* __restrict__ Wq, const float* __restrict__ Wk,
                const float* __restrict__ Wv, const float* __restrict__ Wo) {
    const float* srcs[4] = {Wq, Wk, Wv, Wo};
    const float* W = srcs[blockIdx.z];
    __half* oT = g_wf[blockIdx.z];
    __shared__ float t[32][33];
    int tx = threadIdx.x, ty = threadIdx.y;
    int n0 = blockIdx.x * 32, k0 = blockIdx.y * 32;
#pragma unroll
    for (int r = 0; r < 4; r++)
        t[ty + r * 8][tx] = W[(size_t)(k0 + ty + r * 8) * Dd + n0 + tx];
    __syncthreads();
#pragma unroll
    for (int r = 0; r < 4; r++) {
        int n = n0 + ty + r * 8;
        oT[(size_t)n * Dd + k0 + tx] = __float2half_rn(t[tx][ty + r * 8]);
    }
}

// ---------------------------------------------------------------------------
// Shared tile constants
// ---------------------------------------------------------------------------
constexpr int ROW64 = 144;
constexpr int ARR64 = 128 * ROW64;         // 18432

// ---------------------------------------------------------------------------
// Merged fp16 QKV projection GEMM: 3-stage pipeline, ONE barrier per chunk.
// (S=3 >= D+2 with prefetch distance 1 -> trailing barrier provably redundant)
// ---------------------------------------------------------------------------
constexpr int F16_BUF_B = 2 * ARR64;               // 36864 per stage
constexpr int F16_SMEM = 3 * F16_BUF_B;            // 110592 (x2 CTAs = 216 KB)

__global__ __launch_bounds__(256, 2)
void gemm_f16_qkv() {
    extern __shared__ char smem[];
    const uint32_t sbase = smem_u32(smem);
    const int tid = threadIdx.x;
    const int lane = tid & 31;
    const int wid = tid >> 5;
    const int wm = wid >> 2;
    const int wn = wid & 3;
    const int bm = blockIdx.y * 128;
    const int bn = blockIdx.x * 128;
    const int z = blockIdx.z;

    const __half* A = g_qkvf[z];
    const __half* B = g_wf[z];
    __half* Chf = g_QKV[z];
    const float escale = (z == 0) ? CEXP : 1.0f;

    auto load_chunk = [&](int c, int b) {
        const int k0 = c * 64;
        const uint32_t dst0 = sbase + b * F16_BUF_B;
        const int row = tid >> 1;
        const __half* srcs[2] = {A + (size_t)(bm + row) * Dd + k0,
                                 B + (size_t)(bn + row) * Dd + k0};
#pragma unroll
        for (int a2 = 0; a2 < 2; a2++) {
#pragma unroll
            for (int j = 0; j < 4; j++) {
                int cch = (tid & 1) * 4 + j;
                cp16(dst0 + a2 * ARR64 + row * ROW64 + cch * 16,
                     srcs[a2] + cch * 8);
            }
        }
        cp_commit();
    };

    float acc[4][4][4];
#pragma unroll
    for (int i = 0; i < 4; i++)
#pragma unroll
        for (int j = 0; j < 4; j++)
#pragma unroll
            for (int r = 0; r < 4; r++) acc[i][j][r] = 0.0f;

    auto compute = [&](int b) {
        const uint32_t base = sbase + b * F16_BUF_B;
        const uint32_t aB = base;
        const uint32_t bB = base + ARR64;
#pragma unroll
        for (int s = 0; s < 4; s++) {
            const int kb = s * 32;
            uint32_t af[4][4];
#pragma unroll
            for (int i = 0; i < 4; i++)
                ldm_x4(af[i], fragA<ROW64>(aB, wm * 64 + i * 16, kb, lane));
#pragma unroll
            for (int nb = 0; nb < 2; nb++) {
                uint32_t bf[4];
                ldm_x4(bf, fragA<ROW64>(bB, wn * 32 + nb * 16, kb, lane));
#pragma unroll
                for (int i = 0; i < 4; i++) {
                    mma16816h(acc[i][nb * 2 + 0], af[i], bf[0], bf[2]);
                    mma16816h(acc[i][nb * 2 + 1], af[i], bf[1], bf[3]);
                }
            }
        }
    };

    constexpr int NCHUNK = Dd / 64;   // 16
    load_chunk(0, 0);
    for (int c = 0; c < NCHUNK; c++) {
        if (c + 1 < NCHUNK) {
            load_chunk(c + 1, (c + 1) % 3);
            cp_wait<1>();
        } else {
            cp_wait<0>();
        }
        __syncthreads();          // single barrier per chunk
        compute(c % 3);
    }

    const int g = lane >> 2;
    const int tg = lane & 3;
#pragma unroll
    for (int i = 0; i < 4; i++) {
        int r0 = bm + wm * 64 + i * 16 + g;
#pragma unroll
        for (int j = 0; j < 4; j++) {
            int col = bn + wn * 32 + j * 8 + tg * 2;
            int h = col >> 6, dk = col & 63;
#pragma unroll
            for (int half = 0; half < 2; half++) {
                int r = r0 + half * 8;
                int b_ = r >> 11, s = r & 2047;
                size_t addr = (((size_t)(b_ * Hh + h)) * Ss + s) * DK + dk;
                *(uint32_t*)(Chf + addr) =
                    packh2(acc[i][j][half * 2] * escale,
                           acc[i][j][half * 2 + 1] * escale);
            }
        }
    }
}

// ---------------------------------------------------------------------------
// Wo GEMM: fp16-split 2-product, 2-stage, occ 2 (unchanged from R16).
// ---------------------------------------------------------------------------
constexpr int WO_BUF_B = 3 * ARR64;                // 55296
constexpr int WO_SMEM = 2 * WO_BUF_B;              // 110592

__global__ __launch_bounds__(256, 2)
void gemm_wo(const __half* __restrict__ Ahi, const __half* __restrict__ Alo,
             const __half* __restrict__ B, float* __restrict__ C) {
    extern __shared__ char smem[];
    const uint32_t sbase = smem_u32(smem);
    const int tid = threadIdx.x;
    const int lane = tid & 31;
    const int wid = tid >> 5;
    const int wm = wid >> 2;
    const int wn = wid & 3;
    const int bm = blockIdx.y * 128;
    const int bn = blockIdx.x * 128;

    auto load_chunk = [&](int c, int b) {
        const int k0 = c * 64;
        const uint32_t dst0 = sbase + b * WO_BUF_B;
        const int row = tid >> 1;
        const __half* srcs[3] = {Ahi + (size_t)(bm + row) * Dd + k0,
                                 Alo + (size_t)(bm + row) * Dd + k0,
                                 B + (size_t)(bn + row) * Dd + k0};
#pragma unroll
        for (int a3 = 0; a3 < 3; a3++) {
#pragma unroll
            for (int j = 0; j < 4; j++) {
                int cch = (tid & 1) * 4 + j;
                cp16(dst0 + a3 * ARR64 + row * ROW64 + cch * 16,
                     srcs[a3] + cch * 8);
            }
        }
        cp_commit();
    };

    float acc[4][4][4];
#pragma unroll
    for (int i = 0; i < 4; i++)
#pragma unroll
        for (int j = 0; j < 4; j++)
#pragma unroll
            for (int r = 0; r < 4; r++) acc[i][j][r] = 0.0f;

    auto compute = [&](int b) {
        const uint32_t base = sbase + b * WO_BUF_B;
        const uint32_t aHiB = base;
        const uint32_t aLoB = base + ARR64;
        const uint32_t bB = base + 2 * ARR64;
#pragma unroll
        for (int s = 0; s < 4; s++) {
            const int kb = s * 32;
            uint32_t ahi[4][4], alo[4][4];
#pragma unroll
            for (int i = 0; i < 4; i++) {
                ldm_x4(ahi[i], fragA<ROW64>(aHiB, wm * 64 + i * 16, kb, lane));
                ldm_x4(alo[i], fragA<ROW64>(aLoB, wm * 64 + i * 16, kb, lane));
            }
#pragma unroll
            for (int nb = 0; nb < 2; nb++) {
                uint32_t bf[4];
                ldm_x4(bf, fragA<ROW64>(bB, wn * 32 + nb * 16, kb, lane));
#pragma unroll
                for (int i = 0; i < 4; i++) {
                    mma16816h(acc[i][nb * 2 + 0], ahi[i], bf[0], bf[2]);
                    mma16816h(acc[i][nb * 2 + 1], ahi[i], bf[1], bf[3]);
                    mma16816h(acc[i][nb * 2 + 0], alo[i], bf[0], bf[2]);
                    mma16816h(acc[i][nb * 2 + 1], alo[i], bf[1], bf[3]);
                }
            }
        }
    };

    constexpr int NCHUNK = Dd / 64;   // 16
    load_chunk(0, 0);
    for (int c = 0; c < NCHUNK; c++) {
        if (c + 1 < NCHUNK) {
            load_chunk(c + 1, (c + 1) & 1);
            cp_wait<1>();
        } else {
            cp_wait<0>();
        }
        __syncthreads();
        compute(c & 1);
        __syncthreads();
    }

    const int g = lane >> 2;
    const int tg = lane & 3;
#pragma unroll
    for (int i = 0; i < 4; i++) {
        int r0 = bm + wm * 64 + i * 16 + g;
#pragma unroll
        for (int j = 0; j < 4; j++) {
            int col = bn + wn * 32 + j * 8 + tg * 2;
            *(float2*)(C + (size_t)r0 * Dd + col) =
                make_float2(acc[i][j][0], acc[i][j][1]);
            *(float2*)(C + (size_t)(r0 + 8) * Dd + col) =
                make_float2(acc[i][j][2], acc[i][j][3]);
        }
    }
}

// ---------------------------------------------------------------------------
// Tensor-core flash attention: 4-stage pipeline, ONE barrier per tile.
// (S=4 >= D+2 with prefetch distance 2 -> trailing barrier redundant)
// Fixed-shift softmax (Q pre-scaled), QK/PV 1-product, L via ones-column.
// ---------------------------------------------------------------------------
constexpr int AROW = 144;
constexpr int VROW = 176;
constexpr int Q_TILE_B = 128 * AROW;             // 18432
constexpr int K_TILE_B = 64 * AROW;              // 9216
constexpr int V_TILE_B = 64 * VROW;              // 11264
constexpr int ATT_BUF_B = K_TILE_B + V_TILE_B;   // 20480
constexpr int NSTAGE = 4;
constexpr int ATT_SMEM = Q_TILE_B + NSTAGE * ATT_BUF_B;  // 100352
constexpr uint32_t ONES2 = 0x3C003C00u;

__global__ __launch_bounds__(256, 2)
void attn_mma() {
    extern __shared__ char smem[];
    const uint32_t sb = smem_u32(smem);
    const int tid = threadIdx.x;
    const int lane = tid & 31;
    const int w = tid >> 5;
    const int bh = blockIdx.y;
    const int qt = blockIdx.x;
    const int b = bh >> 4, h = bh & 15;

    const __half* Qg = g_QKV[0] + (size_t)bh * Ss * DK + qt * 128 * DK;
    const __half* Kg = g_QKV[1] + (size_t)bh * Ss * DK;
    const __half* Vg = g_QKV[2] + (size_t)bh * Ss * DK;

    const uint32_t sQ = sb;

    auto load_kv = [&](int kt, int buf) {
        const uint32_t base = sb + Q_TILE_B + buf * ATT_BUF_B;
        {
            const char* src = (const char*)Kg + (size_t)kt * 64 * DK * 2;
#pragma unroll
            for (int p = 0; p < 2; p++) {
                int idx = tid + p * 256;
                int r = idx >> 3, c = idx & 7;
                cp16(base + r * AROW + c * 16, src + (r * DK + c * 8) * 2);
            }
        }
        {
            const char* src = (const char*)Vg + (size_t)kt * 64 * DK * 2;
#pragma unroll
            for (int p = 0; p < 2; p++) {
                int idx = tid + p * 256;
                int r = idx >> 3, c = idx & 7;
                cp16(base + K_TILE_B + r * VROW + c * 16,
                     src + (r * DK + c * 8) * 2);
            }
        }
        cp_commit();
    };

    // Q tile + ones columns (all 4 stages: 4 x 64 rows = 256 threads)
#pragma unroll
    for (int p = 0; p < 4; p++) {
        int idx = tid + p * 256;
        int r = idx >> 3, c = idx & 7;
        cp16(sQ + r * AROW + c * 16, Qg + r * DK + c * 8);
    }
    {
        int r = tid & 63, buf = tid >> 6;   // 4 stages x 64 rows
        uint32_t addr = sb + Q_TILE_B + buf * ATT_BUF_B + K_TILE_B + r * VROW + 128;
        asm volatile("st.shared.v4.b32 [%0], {%1, %1, %1, %1};"
                     :: "r"(addr), "r"(ONES2) : "memory");
    }
    load_kv(0, 0);
    load_kv(1, 1);
    cp_wait<1>();        // stage 0 (and Q) complete
    __syncthreads();

    uint32_t qf[4][4];
#pragma unroll
    for (int s = 0; s < 4; s++)
        ldm_x4(qf[s], fragA<AROW>(sQ, w * 16, s * 32, lane));

    float Oacc[8][4];
    float Lacc[4];
#pragma unroll
    for (int j = 0; j < 8; j++)
#pragma unroll
        for (int r = 0; r < 4; r++) Oacc[j][r] = 0.0f;
#pragma unroll
    for (int r = 0; r < 4; r++) Lacc[r] = 0.0f;

    constexpr int NT = Ss / 64;   // 32
    for (int kt = 0; kt < NT; kt++) {
        if (kt + 2 < NT) {
            load_kv(kt + 2, (kt + 2) & 3);
            cp_wait<2>();             // tile kt complete (kt+1, kt+2 pending)
        } else if (kt + 1 < NT) {
            cp_wait<1>();
        } else {
            cp_wait<0>();
        }
        __syncthreads();              // single barrier per tile

        const uint32_t base = sb + Q_TILE_B + (kt & 3) * ATT_BUF_B;
        const uint32_t kT = base, vT = base + K_TILE_B;

        float sfr[8][4];
#pragma unroll
        for (int j = 0; j < 8; j++)
#pragma unroll
            for (int r = 0; r < 4; r++) sfr[j][r] = 0.0f;

#pragma unroll
        for (int s = 0; s < 4; s++) {
            const int kb = s * 32;
#pragma unroll
            for (int nb = 0; nb < 4; nb++) {
                uint32_t k4[4];
                ldm_x4(k4, fragA<AROW>(kT, nb * 16, kb, lane));
                mma16816h(sfr[nb * 2 + 0], qf[s], k4[0], k4[2]);
                mma16816h(sfr[nb * 2 + 1], qf[s], k4[1], k4[3]);
            }
        }

        uint32_t p2[8][2];
#pragma unroll
        for (int j = 0; j < 8; j++) {
            uint32_t t0 = packh2(sfr[j][0], sfr[j][1]);
            uint32_t t1 = packh2(sfr[j][2], sfr[j][3]);
            p2[j][0] = ex2h2(t0);
            p2[j][1] = ex2h2(t1);
        }

#pragma unroll
        for (int st = 0; st < 4; st++) {
            uint32_t pa[4] = {p2[2 * st][0], p2[2 * st][1],
                              p2[2 * st + 1][0], p2[2 * st + 1][1]};
#pragma unroll
            for (int nb = 0; nb < 4; nb++) {
                uint32_t v4[4];
                ldm_x4_t(v4, fragT<VROW>(vT, st * 16, nb * 32, lane));
                mma16816h(Oacc[nb * 2 + 0], pa, v4[0], v4[2]);
                mma16816h(Oacc[nb * 2 + 1], pa, v4[1], v4[3]);
            }
            mma16816h(Lacc, pa, ONES2, ONES2);
        }
    }

    // ---- epilogue: normalize, split to fp16 hi/lo, write [B,S,D]
    const float inv0 = 1.0f / Lacc[0];
    const float inv1 = 1.0f / Lacc[2];
    const int g = lane >> 2;
    const int t = lane & 3;
    const int row0 = qt * 128 + w * 16 + g;
    const size_t gbase0 = ((size_t)b * Ss + row0) * Dd + h * 64;
    const size_t gbase1 = gbase0 + 8 * Dd;
#pragma unroll
    for (int j = 0; j < 8; j++) {
        int col = j * 8 + t * 2;
        float o00 = Oacc[j][0] * inv0, o01 = Oacc[j][1] * inv0;
        float o10 = Oacc[j][2] * inv1, o11 = Oacc[j][3] * inv1;
        __half h00 = __float2half_rn(o00), h01 = __float2half_rn(o01);
        __half h10 = __float2half_rn(o10), h11 = __float2half_rn(o11);
        *(uint32_t*)(g_ohf + gbase0 + col) =
            packh2(__half2float(h00), __half2float(h01));
        *(uint32_t*)(g_olf + gbase0 + col) =
            packh2(o00 - __half2float(h00), o01 - __half2float(h01));
        *(uint32_t*)(g_ohf + gbase1 + col) =
            packh2(__half2float(h10), __half2float(h11));
        *(uint32_t*)(g_olf + gbase1 + col) =
            packh2(o10 - __half2float(h10), o11 - __half2float(h11));
    }
}

// ---------------------------------------------------------------------------
// Launch
// ---------------------------------------------------------------------------
extern "C" void kernel_launch(void* const* d_in, const int* in_sizes, int n_in,
                              void* d_out, int out_size) {
    const float* q  = (const float*)d_in[0];
    const float* k  = (const float*)d_in[1];
    const float* v  = (const float*)d_in[2];
    const float* Wq = (const float*)d_in[3];
    const float* Wk = (const float*)d_in[4];
    const float* Wv = (const float*)d_in[5];
    const float* Wo = (const float*)d_in[6];
    float* out = (float*)d_out;

    __half *ohf, *olf, *wf;
    cudaGetSymbolAddress((void**)&ohf, g_ohf);
    cudaGetSymbolAddress((void**)&olf, g_olf);
    cudaGetSymbolAddress((void**)&wf, g_wf);
    const size_t WSTRIDE = (size_t)Dd * Dd;

    cudaFuncSetAttribute(attn_mma,
                         cudaFuncAttributeMaxDynamicSharedMemorySize, ATT_SMEM);
    cudaFuncSetAttribute(gemm_f16_qkv,
                         cudaFuncAttributeMaxDynamicSharedMemorySize, F16_SMEM);
    cudaFuncSetAttribute(gemm_wo,
                         cudaFuncAttributeMaxDynamicSharedMemorySize, WO_SMEM);

    const int cvt_blocks = Mrows * Dd / (256 * 4);
    cvt_f16_3<<<dim3(cvt_blocks, 1, 3), 256>>>(q, k, v);

    dim3 tB(32, 8), tG4(Dd / 32, Dd / 32, 4);
    cvt_f16T_4<<<tG4, tB>>>(Wq, Wk, Wv, Wo);

    gemm_f16_qkv<<<dim3(Dd / 128, Mrows / 128, 3), 256, F16_SMEM>>>();

    attn_mma<<<dim3(Ss / 128, Bb * Hh), 256, ATT_SMEM>>>();

    gemm_wo<<<dim3(Dd / 128, Mrows / 128), 256, WO_SMEM>>>(
        ohf, olf, wf + 3 * WSTRIDE, out);
}